// round 3
// baseline (speedup 1.0000x reference)
#include <cuda_runtime.h>

// Problem constants (fixed by the reference setup_inputs)
#define BB 4
#define HH 384
#define WW 512
#define CC 64
#define CH8 (CC / 8)        // 8 chunks of 8 floats per pixel
#define PIXB 32             // pixels per block
#define THREADS 256         // 32 pixels x 8 threads; one 8-float chunk each

struct __align__(32) f8 { float v[8]; };

__device__ __forceinline__ f8 ldg256(const float* p) {
    f8 r;
    asm volatile("ld.global.nc.v8.f32 {%0,%1,%2,%3,%4,%5,%6,%7}, [%8];"
                 : "=f"(r.v[0]), "=f"(r.v[1]), "=f"(r.v[2]), "=f"(r.v[3]),
                   "=f"(r.v[4]), "=f"(r.v[5]), "=f"(r.v[6]), "=f"(r.v[7])
                 : "l"(p));
    return r;
}

__device__ __forceinline__ void stg256_cs(float* p, const f8& r) {
    asm volatile("st.global.cs.v8.f32 [%0], {%1,%2,%3,%4,%5,%6,%7,%8};"
                 :: "l"(p),
                    "f"(r.v[0]), "f"(r.v[1]), "f"(r.v[2]), "f"(r.v[3]),
                    "f"(r.v[4]), "f"(r.v[5]), "f"(r.v[6]), "f"(r.v[7])
                 : "memory");
}

__global__ void __launch_bounds__(THREADS)
warp_bilinear_kernel(const float2* __restrict__ flow,    // [B,H,W] of float2
                     const float*  __restrict__ feat,    // [B,H,W,C]
                     const float*  __restrict__ mask,    // [H,W]
                     float*        __restrict__ out)     // [B,H,W,C]
{
    const int lane = threadIdx.x & 7;          // chunk index [0,8): 8 floats each
    const int pi   = threadIdx.x >> 3;         // pixel within block [0,32)
    const int px   = blockIdx.x * PIXB + pi;
    const int py   = blockIdx.y;
    const int b    = blockIdx.z;

    const int hw  = py * WW + px;
    const int pix = b * (HH * WW) + hw;

    const float2 fl = __ldcs(&flow[pix]);
    const float xt = (float)px + fl.x;
    const float yt = (float)py + fl.y;

    // Faithful to reference arithmetic: (2*t/(D-1) - 1 + 1) * 0.5 * D
    const float x = (2.0f * xt / (float)(WW - 1) - 1.0f + 1.0f) * 0.5f * (float)WW;
    const float y = (2.0f * yt / (float)(HH - 1) - 1.0f + 1.0f) * 0.5f * (float)HH;

    int x0 = (int)floorf(x);
    int y0 = (int)floorf(y);
    x0 = min(max(x0, 0), WW - 1);
    y0 = min(max(y0, 0), HH - 1);
    const int x1 = min(x0 + 1, WW - 1);
    const int y1 = min(y0 + 1, HH - 1);

    const float x0f = (float)x0, x1f = (float)x1;
    const float y0f = (float)y0, y1f = (float)y1;

    const float m = mask[hw];
    const float wam = (x1f - x) * (y1f - y) * m;
    const float wbm = (x1f - x) * (y - y0f) * m;
    const float wcm = (x - x0f) * (y1f - y) * m;
    const float wdm = (x - x0f) * (y - y0f) * m;

    const float* fbase = feat + (long)b * (HH * WW) * CC + lane * 8;
    const f8 fa = ldg256(fbase + (y0 * WW + x0) * CC);
    const f8 fb = ldg256(fbase + (y1 * WW + x0) * CC);
    const f8 fc = ldg256(fbase + (y0 * WW + x1) * CC);
    const f8 fd = ldg256(fbase + (y1 * WW + x1) * CC);

    f8 r;
#pragma unroll
    for (int i = 0; i < 8; ++i)
        r.v[i] = wam * fa.v[i] + wbm * fb.v[i] + wcm * fc.v[i] + wdm * fd.v[i];

    stg256_cs(out + (long)pix * CC + lane * 8, r);
}

extern "C" void kernel_launch(void* const* d_in, const int* in_sizes, int n_in,
                              void* d_out, int out_size)
{
    const float2* flow = (const float2*)d_in[0];   // w: [B,H,W,2]
    const float*  feat = (const float*)d_in[1];    // feature: [B,H,W,C]
    const float*  mask = (const float*)d_in[2];    // mask: [H,W]
    float* out = (float*)d_out;

    dim3 grid(WW / PIXB, HH, BB);                  // (16, 384, 4)
    warp_bilinear_kernel<<<grid, THREADS>>>(flow, feat, mask, out);
}

// round 4
// speedup vs baseline: 1.2000x; 1.2000x over previous
#include <cuda_runtime.h>

// Problem constants (fixed by the reference setup_inputs)
#define BB 4
#define HH 384
#define WW 512
#define CC 64
#define CH4 (CC / 4)        // 16 float4 chunks per pixel
#define PIXB 32             // pixels per block
#define THREADS 256         // 32 pixels x 8 threads; each thread does 2 float4 chunks

__global__ void __launch_bounds__(THREADS, 8)
warp_bilinear_kernel(const float2* __restrict__ flow,    // [B,H,W] of float2
                     const float4* __restrict__ feat,    // [B,H,W,C/4] of float4
                     const float*  __restrict__ mask,    // [H,W]
                     float4*       __restrict__ out)     // [B,H,W,C/4]
{
    const unsigned lane = threadIdx.x & 7u;        // chunk group: handles lane and lane+8
    const unsigned pi   = threadIdx.x >> 3;        // pixel within block [0,32)
    const unsigned px   = blockIdx.x * PIXB + pi;
    const unsigned py   = blockIdx.y;
    const unsigned b    = blockIdx.z;

    const unsigned hw  = py * WW + px;
    const unsigned pix = b * (HH * WW) + hw;

    const float2 fl = __ldcs(&flow[pix]);
    const float xt = (float)px + fl.x;
    const float yt = (float)py + fl.y;

    // Faithful to reference arithmetic: (2*t/(D-1) - 1 + 1) * 0.5 * D
    const float x = (2.0f * xt / (float)(WW - 1) - 1.0f + 1.0f) * 0.5f * (float)WW;
    const float y = (2.0f * yt / (float)(HH - 1) - 1.0f + 1.0f) * 0.5f * (float)HH;

    int x0i = (int)floorf(x);
    int y0i = (int)floorf(y);
    x0i = min(max(x0i, 0), WW - 1);
    y0i = min(max(y0i, 0), HH - 1);
    const int x1i = min(x0i + 1, WW - 1);
    const int y1i = min(y0i + 1, HH - 1);

    const float x0f = (float)x0i, x1f = (float)x1i;
    const float y0f = (float)y0i, y1f = (float)y1i;

    const float m = mask[hw];
    const float wam = (x1f - x) * (y1f - y) * m;
    const float wbm = (x1f - x) * (y - y0f) * m;
    const float wcm = (x - x0f) * (y1f - y) * m;
    const float wdm = (x - x0f) * (y - y0f) * m;

    // 32-bit indexing (feature is 201 MB; all element offsets < 2^26)
    const unsigned base = b * (HH * WW) * CH4 + lane;
    const float4* pa = feat + base + (unsigned)(y0i * WW + x0i) * CH4;
    const float4* pb = feat + base + (unsigned)(y1i * WW + x0i) * CH4;
    const float4* pc = feat + base + (unsigned)(y0i * WW + x1i) * CH4;
    const float4* pd = feat + base + (unsigned)(y1i * WW + x1i) * CH4;

    // Two independent chunk sets (lane, lane+8) -> 8 outstanding gathers
    const float4 fa0 = pa[0], fa1 = pa[8];
    const float4 fb0 = pb[0], fb1 = pb[8];
    const float4 fc0 = pc[0], fc1 = pc[8];
    const float4 fd0 = pd[0], fd1 = pd[8];

    float4 r0, r1;
    r0.x = wam * fa0.x + wbm * fb0.x + wcm * fc0.x + wdm * fd0.x;
    r0.y = wam * fa0.y + wbm * fb0.y + wcm * fc0.y + wdm * fd0.y;
    r0.z = wam * fa0.z + wbm * fb0.z + wcm * fc0.z + wdm * fd0.z;
    r0.w = wam * fa0.w + wbm * fb0.w + wcm * fc0.w + wdm * fd0.w;

    r1.x = wam * fa1.x + wbm * fb1.x + wcm * fc1.x + wdm * fd1.x;
    r1.y = wam * fa1.y + wbm * fb1.y + wcm * fc1.y + wdm * fd1.y;
    r1.z = wam * fa1.z + wbm * fb1.z + wcm * fc1.z + wdm * fd1.z;
    r1.w = wam * fa1.w + wbm * fb1.w + wcm * fc1.w + wdm * fd1.w;

    float4* po = out + pix * CH4 + lane;
    __stcs(po + 0, r0);
    __stcs(po + 8, r1);
}

extern "C" void kernel_launch(void* const* d_in, const int* in_sizes, int n_in,
                              void* d_out, int out_size)
{
    const float2* flow = (const float2*)d_in[0];   // w: [B,H,W,2]
    const float4* feat = (const float4*)d_in[1];   // feature: [B,H,W,C]
    const float*  mask = (const float*)d_in[2];    // mask: [H,W]
    float4* out = (float4*)d_out;

    dim3 grid(WW / PIXB, HH, BB);                  // (16, 384, 4)
    warp_bilinear_kernel<<<grid, THREADS>>>(flow, feat, mask, out);
}